// round 16
// baseline (speedup 1.0000x reference)
#include <cuda_runtime.h>
#include <cuda_fp16.h>
#include <math.h>

// Dimensions
#define D2i 1024   // 2H
#define D4i 2048   // 4H
#define G3i 6144   // 3*D4
#define Hi  512
#define Vi  32000
#define Mi  32
#define Ni  4096
#define Li  64

#define NBLK 112
#define NTHR 1024
#define LBLK 500      // logits blocks (Vi/64)

// ---------------- device scratch ----------------
__device__ float  g_hpart[128][D2i];
__device__ float  g_h[D2i];
__device__ float  g_uah[D2i];
__device__ float  g_hbuf[2][D4i];
__device__ float2 g_srow[D2i];
__device__ float2 g_gi2[G3i];          // wih2-row @ (d0,d1) partials (attn warps -> GRU warps)
__device__ float  g_pre_gi[Li][G3i];
__device__ float  g_pre_r[Li][D2i];
__device__ float  g_R[Li][Hi];
__device__ float  g_lpart[LBLK * Li];
__device__ unsigned int g_bar_count = 0;
__device__ volatile unsigned int g_bar_gen = 0;

// fp16 weights, contiguous rows, gate/pair-interleaved ROW ORDER:
__device__ __half g_whh_h [G3i * D4i];   // dst row 3k+g = whh row (g*2048+k)
__device__ __half g_wih2_h[G3i * D2i];   // dst row 3k+g = wih row (g*2048+k), cols D2..D4
__device__ __half g_wa_h  [D2i * D2i];
__device__ __half g_ur_h  [D2i * D2i];   // dst row 2i+s = ur row (s*512+i)
__device__ __half g_vr_h  [D2i * D4i];   // dst row 2i+s = vr row (s*512+i)
__device__ __half g_wo_h  [Vi * Hi];     // plain row-major half copy of w_o

__device__ __forceinline__ float warp_sum(float v) {
#pragma unroll
    for (int o = 16; o; o >>= 1) v += __shfl_xor_sync(0xffffffffu, v, o);
    return v;
}

// atomic grid barrier: one arrival atomic + one polled line, nanosleep backoff
__device__ __forceinline__ void grid_bar() {
    __threadfence();
    __syncthreads();
    if (threadIdx.x == 0) {
        unsigned int gen = g_bar_gen;
        if (atomicAdd(&g_bar_count, 1u) == NBLK - 1) {
            g_bar_count = 0;
            __threadfence();
            g_bar_gen = gen + 1;
        } else {
            while (g_bar_gen == gen) { __nanosleep(32); }
        }
    }
    __syncthreads();
}

// fp16 dot, HFMA2, per-lane partial (caller warp_sums). Weights via __ldcg.
template<int NM>
__device__ __forceinline__ float dot_hh(const uint4* __restrict__ w,
                                        const uint4* __restrict__ v, int lane) {
    float acc = 0.f;
#pragma unroll
    for (int m = 0; m < NM; m += 2) {
        uint4 u0 = __ldcg(&w[lane + 32 * m]);
        uint4 x0 = v[lane + 32 * m];
        uint4 u1 = __ldcg(&w[lane + 32 * (m + 1)]);
        uint4 x1 = v[lane + 32 * (m + 1)];
        const __half2* a = (const __half2*)&u0;
        const __half2* b = (const __half2*)&x0;
        __half2 s = __hmul2(a[0], b[0]);
        s = __hfma2(a[1], b[1], s);
        s = __hfma2(a[2], b[2], s);
        s = __hfma2(a[3], b[3], s);
        const __half2* c = (const __half2*)&u1;
        const __half2* d = (const __half2*)&x1;
        s = __hfma2(c[0], d[0], s);
        s = __hfma2(c[1], d[1], s);
        s = __hfma2(c[2], d[2], s);
        s = __hfma2(c[3], d[3], s);
        float2 f = __half22float2(s);
        acc += f.x + f.y;
    }
    return acc;
}
// one weight row vs two smem vectors (weights read once), per-lane partial pair
template<int NM>
__device__ __forceinline__ float2 dot_hh2(const uint4* __restrict__ w,
                                          const uint4* __restrict__ v0,
                                          const uint4* __restrict__ v1, int lane) {
    float a0 = 0.f, a1 = 0.f;
#pragma unroll
    for (int m = 0; m < NM; m += 2) {
        uint4 u0 = __ldcg(&w[lane + 32 * m]);
        uint4 u1 = __ldcg(&w[lane + 32 * (m + 1)]);
        uint4 p0 = v0[lane + 32 * m], p1 = v0[lane + 32 * (m + 1)];
        uint4 q0 = v1[lane + 32 * m], q1 = v1[lane + 32 * (m + 1)];
        const __half2* a = (const __half2*)&u0;
        const __half2* c = (const __half2*)&u1;
        {
            const __half2* b0 = (const __half2*)&p0;
            const __half2* b1 = (const __half2*)&p1;
            __half2 s = __hmul2(a[0], b0[0]);
            s = __hfma2(a[1], b0[1], s);
            s = __hfma2(a[2], b0[2], s);
            s = __hfma2(a[3], b0[3], s);
            s = __hfma2(c[0], b1[0], s);
            s = __hfma2(c[1], b1[1], s);
            s = __hfma2(c[2], b1[2], s);
            s = __hfma2(c[3], b1[3], s);
            float2 f = __half22float2(s);
            a0 += f.x + f.y;
        }
        {
            const __half2* b0 = (const __half2*)&q0;
            const __half2* b1 = (const __half2*)&q1;
            __half2 s = __hmul2(a[0], b0[0]);
            s = __hfma2(a[1], b0[1], s);
            s = __hfma2(a[2], b0[2], s);
            s = __hfma2(a[3], b0[3], s);
            s = __hfma2(c[0], b1[0], s);
            s = __hfma2(c[1], b1[1], s);
            s = __hfma2(c[2], b1[2], s);
            s = __hfma2(c[3], b1[3], s);
            float2 f = __half22float2(s);
            a1 += f.x + f.y;
        }
    }
    return make_float2(a0, a1);
}

// ---------------- conversion helper (row-reordered, contiguous elements) ----------------
__device__ __forceinline__ void cvt_seg(const float* __restrict__ src, __half2* __restrict__ dst,
                                        int rows, int w2shift, int srcLd, int srcOff,
                                        int nG, int G, int gtid, int gstride) {
    int total = rows << w2shift;
    int mask = (1 << w2shift) - 1;
    for (int idx = gtid; idx < total; idx += gstride) {
        int r = idx >> w2shift, e2 = idx & mask;
        int sr = (r % nG) * G + r / nG;
        float2 f = *(const float2*)(src + (size_t)sr * srcLd + srcOff + 2 * e2);
        dst[idx] = __floats2half2_rn(f.x, f.y);
    }
}

// ---------------- fused prologue: pre-GEMMs [0,448) + hpart [448,576) + cvt [576,1168) ----
#define PREPB 1168
#define CVT0  576
__global__ void k_prep(const float* __restrict__ wih, const float* __restrict__ bih,
                       const float* __restrict__ wr,  const float* __restrict__ ans,
                       const float* __restrict__ hq,  const float* __restrict__ hp,
                       const float* __restrict__ whh, const float* __restrict__ wa,
                       const float* __restrict__ ur,  const float* __restrict__ vr,
                       const float* __restrict__ wo,
                       float* __restrict__ pg, float* __restrict__ pr,
                       __half2* p_whh, __half2* p_wih2, __half2* p_wa,
                       __half2* p_ur, __half2* p_vr, __half2* p_wo) {
    __shared__ float As[16][65];
    __shared__ __align__(16) float BsT[64][68];
    int blk = blockIdx.x;
    int tid = threadIdx.x;

    if (blk < 448) {
        // ---- pre-GEMMs (16-row tiles) ----
        const float* A; const float* bias; float* C;
        int lda, crows, k0;
        if (blk < 384) { A = wih; lda = D4i; bias = bih; C = pg; crows = G3i; k0 = blk * 16; }
        else           { A = wr;  lda = D2i; bias = 0;   C = pr; crows = D2i; k0 = (blk - 384) * 16; }
        int tx = tid & 15, ty = tid >> 4;
        float acc[4] = {0.f, 0.f, 0.f, 0.f};
        for (int ch = 0; ch < D2i; ch += 64) {
            for (int i = tid; i < 16 * 64; i += 256) {
                int r = i >> 6, c = i & 63;
                As[r][c] = A[(size_t)(k0 + r) * lda + ch + c];
            }
            for (int i = tid; i < 64 * 64; i += 256) {
                int t = i >> 6, c = i & 63;
                BsT[c][t] = ans[(size_t)t * D2i + ch + c];
            }
            __syncthreads();
#pragma unroll 16
            for (int p = 0; p < 64; p++) {
                float4 bv = *(const float4*)&BsT[p][tx * 4];
                float a = As[ty][p];
                acc[0] += a * bv.x; acc[1] += a * bv.y; acc[2] += a * bv.z; acc[3] += a * bv.w;
            }
            __syncthreads();
        }
        int k = k0 + ty;
        float bb = bias ? bias[k] : 0.f;
#pragma unroll
        for (int j = 0; j < 4; j++)
            C[(size_t)(tx * 4 + j) * crows + k] = acc[j] + bb;
    } else if (blk < CVT0) {
        // ---- pooled-h partials ----
        int b = blk - 448;
        float acc[4] = {0.f, 0.f, 0.f, 0.f};
        for (int r = 0; r < 32; r++) {
            const float* row = hp + (size_t)(b * 32 + r) * D2i;
#pragma unroll
            for (int c = 0; c < 4; c++) acc[c] += row[tid + 256 * c];
        }
        if (b == 0) {
            for (int r = 0; r < Mi; r++) {
                const float* row = hq + (size_t)r * D2i;
#pragma unroll
                for (int c = 0; c < 4; c++) acc[c] += row[tid + 256 * c];
            }
        }
#pragma unroll
        for (int c = 0; c < 4; c++) g_hpart[b][tid + 256 * c] = acc[c];
    } else {
        // ---- weight conversions (grid-strided over the cvt section) ----
        int gtid = (blk - CVT0) * 256 + tid;
        int gstride = (PREPB - CVT0) * 256;
        cvt_seg(whh, p_whh,  G3i, 10, D4i, 0,    3, D4i, gtid, gstride);
        cvt_seg(wih, p_wih2, G3i,  9, D4i, D2i,  3, D4i, gtid, gstride);
        cvt_seg(wa,  p_wa,   D2i,  9, D2i, 0,    1, D2i, gtid, gstride);
        cvt_seg(ur,  p_ur,   D2i,  9, D2i, 0,    2, Hi,  gtid, gstride);
        cvt_seg(vr,  p_vr,   D2i, 10, D4i, 0,    2, Hi,  gtid, gstride);
        cvt_seg(wo,  p_wo,   Vi,   8, Hi,  0,    1, Vi,  gtid, gstride);
    }
}

__global__ void k_hreduce() {
    int j = blockIdx.x * 256 + threadIdx.x;
    float s = 0.f;
    for (int b = 0; b < 128; b++) s += g_hpart[b][j];
    g_h[j] = s;
}

// ---------------- uah + d0 (fp32) ----------------
__device__ __forceinline__ float dot4f(float4 a, float4 b) {
    return a.x * b.x + a.y * b.y + a.z * b.z + a.w * b.w;
}
__global__ void k_uah_d0(const float* __restrict__ ua,
                         const float* __restrict__ hq, const float* __restrict__ hp,
                         const float* __restrict__ wd, const float* __restrict__ bd) {
    int lane = threadIdx.x & 31;
    if (blockIdx.x < 128) {
        int k = blockIdx.x * 8 + (threadIdx.x >> 5);
        const float4* row = (const float4*)(ua + (size_t)k * D2i);
        const float4* h4  = (const float4*)g_h;
        float acc = 0.f;
#pragma unroll
        for (int m = 0; m < 8; m++) acc += dot4f(row[lane + 32 * m], h4[lane + 32 * m]);
        acc = warp_sum(acc);
        if (!lane) g_uah[k] = acc;
    } else {
        int k = (blockIdx.x - 128) * 8 + (threadIdx.x >> 5);
        const float4* row = (const float4*)(wd + (size_t)k * D2i);
        const float4* q4 = (const float4*)hq;
        const float4* p4 = (const float4*)hp;
        float a0 = 0.f, a1 = 0.f;
#pragma unroll
        for (int m = 0; m < 8; m++) {
            float4 w = row[lane + 32 * m];
            a0 += dot4f(w, q4[lane + 32 * m]);
            a1 += dot4f(w, p4[lane + 32 * m]);
        }
        a0 = warp_sum(a0); a1 = warp_sum(a1);
        if (!lane) {
            float b = bd[k];
            g_hbuf[0][k]       = tanhf(a0 + b);
            g_hbuf[0][D2i + k] = tanhf(a1 + b);
        }
    }
}

// ---------------- persistent decode: byte-balanced roles ----------------
// tau = wid*NBLK + blockIdx:
//   GRU  (tau<2048,k=tau): whh 3 rows @ d (12KB); post: read g_gi2[3k..3k+2], combine+cell
//   ATTN (2048..3071,j):   wa row @ (d0,d1) -> score FIRST (2KB), then wih2 rows
//                          6j..6j+5 @ (d0,d1) -> g_gi2 (12KB)   [total 14KB]
//   R    (3072..3583,i):   finish R[t-1] + new ur@(d0,d1) (12KB); post: fold A0/A1
__global__ void __launch_bounds__(NTHR, 1) k_decode(
    const float* __restrict__ vv, const float* __restrict__ bhh)
{
    __shared__ __align__(16) __half sdh[D4i];
    __shared__ float sred0[32], sred1[32];

    int tid = threadIdx.x, lane = tid & 31, wid = tid >> 5;
    int tau = wid * NBLK + blockIdx.x;

    float hr = 0.f, hz = 0.f, hn = 0.f;
    float2 gr2 = make_float2(0.f, 0.f);   // R-warp scratch (A1-side ur partials)
    float puLo = 0.f, puHi = 0.f;

    for (int t = 0; t < Li; t++) {
        int p = t & 1, q = p ^ 1;
        for (int j = tid; j < D4i; j += NTHR)
            sdh[j] = __float2half(__ldcg(&g_hbuf[p][j]));
        __syncthreads();
        const uint4* vd  = (const uint4*)sdh;
        const uint4* vd0 = vd;
        const uint4* vd1 = (const uint4*)(sdh + D2i);

        if (tau < 2048) {
            const uint4* wh = (const uint4*)(g_whh_h + (size_t)tau * 3 * D4i);
            hr = dot_hh<8>(wh,                 vd, lane);
            hz = dot_hh<8>(wh + (D4i >> 3),    vd, lane);
            hn = dot_hh<8>(wh + (D4i >> 2),    vd, lane);
        } else if (tau < 3072) {
            int j = tau - 2048;
            // score first (frees consumers early)
            const uint4* w = (const uint4*)(g_wa_h + (size_t)j * D2i);
            float2 s = dot_hh2<4>(w, vd0, vd1, lane);
            s.x = warp_sum(s.x); s.y = warp_sum(s.y);
            if (!lane) {
                float vk = vv[j], uh = g_uah[j];
                float2 o;
                o.x = vk * tanhf(s.x + uh);
                o.y = vk * tanhf(s.y + uh);
                __stcg(&g_srow[j], o);
            }
            // wih2 rows 6j..6j+5 (gate-interleaved: GRU rows 2j,2j+1)
            const uint4* pw = (const uint4*)(g_wih2_h + (size_t)j * 6 * D2i);
#pragma unroll
            for (int r = 0; r < 6; r++) {
                float2 gi = dot_hh2<4>(pw + r * (D2i >> 3), vd0, vd1, lane);
                gi.x = warp_sum(gi.x); gi.y = warp_sum(gi.y);
                if (!lane) __stcg(&g_gi2[j * 6 + r], gi);
            }
        } else {
            int i = tau - 3072;
            if (t > 0) {
                const uint4* vp = (const uint4*)(g_vr_h + (size_t)i * 2 * D4i);
                float lo = warp_sum(puLo + dot_hh<8>(vp,              vd, lane));
                float hi = warp_sum(puHi + dot_hh<8>(vp + (D4i >> 3), vd, lane));
                if (!lane) {
                    int r = t - 1;
                    g_R[r][i] = fmaxf(g_pre_r[r][i] + lo, g_pre_r[r][i + Hi] + hi);
                }
            }
            const uint4* up = (const uint4*)(g_ur_h + (size_t)i * 2 * D2i);
            float2 uLo = dot_hh2<4>(up,              vd0, vd1, lane);
            float2 uHi = dot_hh2<4>(up + (D2i >> 3), vd0, vd1, lane);
            puLo = uLo.x; puHi = uHi.x;
            gr2.x = uLo.y; gr2.y = uHi.y;
        }
        grid_bar();

        // redundant deterministic score reduce
        float2 sv = __ldcg(&g_srow[tid]);          // NTHR == D2i
        float v0 = warp_sum(sv.x);
        float v1 = warp_sum(sv.y);
        if (!lane) { sred0[wid] = v0; sred1[wid] = v1; }
        __syncthreads();
        float s0 = 0.f, s1 = 0.f;
#pragma unroll
        for (int i2 = 0; i2 < 32; i2++) { s0 += sred0[i2]; s1 += sred1[i2]; }
        float mx = fmaxf(s0, s1);
        float e0 = expf(s0 - mx), e1 = expf(s1 - mx);
        float inv = 1.f / (e0 + e1);
        float A0 = e0 * inv, A1 = e1 * inv;

        if (tau < 2048) {
            int k = tau;
            float Sr  = warp_sum(hr);
            float Sz  = warp_sum(hz);
            float Shn = warp_sum(hn);
            if (!lane) {
                float2 gir = __ldcg(&g_gi2[3 * k]);
                float2 giz = __ldcg(&g_gi2[3 * k + 1]);
                float2 gin = __ldcg(&g_gi2[3 * k + 2]);
                float ir = g_pre_gi[t][k]       + A0 * gir.x + A1 * gir.y + Sr + bhh[k];
                float iz = g_pre_gi[t][k + D4i] + A0 * giz.x + A1 * giz.y + Sz + bhh[k + D4i];
                float R = 1.f / (1.f + expf(-ir));
                float Z = 1.f / (1.f + expf(-iz));
                float Nn = tanhf(g_pre_gi[t][k + 2 * D4i] + A0 * gin.x + A1 * gin.y
                                 + R * (Shn + bhh[k + 2 * D4i]));
                float dk = __ldcg(&g_hbuf[p][k]);
                __stcg(&g_hbuf[q][k], (1.f - Z) * Nn + Z * dk);
            }
        } else if (tau >= 3072) {
            puLo = A0 * puLo + A1 * gr2.x;
            puHi = A0 * puHi + A1 * gr2.y;
        }
        grid_bar();
    }

    // tail: R[63] with carried partials and h_64 (g_hbuf[0])
    for (int j = tid; j < D4i; j += NTHR)
        sdh[j] = __float2half(__ldcg(&g_hbuf[0][j]));
    __syncthreads();
    if (tau >= 3072) {
        int i = tau - 3072;
        const uint4* vd = (const uint4*)sdh;
        const uint4* vp = (const uint4*)(g_vr_h + (size_t)i * 2 * D4i);
        float lo = warp_sum(puLo + dot_hh<8>(vp,              vd, lane));
        float hi = warp_sum(puHi + dot_hh<8>(vp + (D4i >> 3), vd, lane));
        if (!lane)
            g_R[Li - 1][i] = fmaxf(g_pre_r[Li - 1][i] + lo, g_pre_r[Li - 1][i + Hi] + hi);
    }
}

// ---------------- logits GEMM: fp16 weights, HFMA2, exp epilogue + partial sums ----------
__global__ void k_logits(float* __restrict__ out) {
    __shared__ __align__(16) __half2 As[64][33];    // k rows x 32 half2 (+pad)
    __shared__ __align__(16) __half2 BsT[32][68];   // p x t (68 half2 = 17 uint4)
    __shared__ float ps[64][17];
    const __half2* wo2 = (const __half2*)g_wo_h;
    const float* Rm = (const float*)g_R;
    int k0 = blockIdx.x * 64;
    int tid = threadIdx.x;
    int tx = tid & 15, ty = tid >> 4;
    float accf[4][4];
#pragma unroll
    for (int i = 0; i < 4; i++)
#pragma unroll
        for (int j = 0; j < 4; j++) accf[i][j] = 0.f;

    const __half2 hz2 = __float2half2_rn(0.f);
    for (int chunk = 0; chunk < 8; chunk++) {       // 8 x 64 ch = 512
        for (int i = tid; i < 64 * 32; i += 256) {
            int r = i >> 5, c = i & 31;
            As[r][c] = wo2[(size_t)(k0 + r) * (Hi / 2) + chunk * 32 + c];
        }
        for (int i = tid; i < 64 * 32; i += 256) {
            int t = i >> 5, c = i & 31;
            float2 f = *(const float2*)(Rm + (size_t)t * Hi + chunk * 64 + 2 * c);
            BsT[c][t] = __floats2half2_rn(f.x, f.y);
        }
        __syncthreads();
        __half2 acch[4][4];
#pragma unroll
        for (int i = 0; i < 4; i++)
#pragma unroll
            for (int j = 0; j < 4; j++) acch[i][j] = hz2;
#pragma unroll
        for (int p = 0; p < 32; p++) {
            uint4 bvu = *(const uint4*)&BsT[p][tx * 4];
            const __half2* bv = (const __half2*)&bvu;
            __half2 av0 = As[ty * 4 + 0][p];
            __half2 av1 = As[ty * 4 + 1][p];
            __half2 av2 = As[ty * 4 + 2][p];
            __half2 av3 = As[ty * 4 + 3][p];
#pragma unroll
            for (int j = 0; j < 4; j++) {
                acch[0][j] = __hfma2(av0, bv[j], acch[0][j]);
                acch[1][j] = __hfma2(av1, bv[j], acch[1][j]);
                acch[2][j] = __hfma2(av2, bv[j], acch[2][j]);
                acch[3][j] = __hfma2(av3, bv[j], acch[3][j]);
            }
            if ((p & 7) == 7) {
#pragma unroll
                for (int i = 0; i < 4; i++)
#pragma unroll
                    for (int j = 0; j < 4; j++) {
                        float2 f = __half22float2(acch[i][j]);
                        accf[i][j] += f.x + f.y;
                        acch[i][j] = hz2;
                    }
            }
        }
        __syncthreads();
    }
    float colsum[4] = {0.f, 0.f, 0.f, 0.f};
#pragma unroll
    for (int i = 0; i < 4; i++) {
        int k = k0 + ty * 4 + i;
#pragma unroll
        for (int j = 0; j < 4; j++) {
            float e = expf(accf[i][j]);
            out[(size_t)(tx * 4 + j) * Vi + k] = e;
            colsum[j] += e;
        }
    }
#pragma unroll
    for (int j = 0; j < 4; j++) ps[tx * 4 + j][ty] = colsum[j];
    __syncthreads();
    if (tid < 64) {
        float s = 0.f;
#pragma unroll
        for (int y = 0; y < 16; y++) s += ps[tid][y];
        g_lpart[blockIdx.x * 64 + tid] = s;
    }
}

__global__ void k_scale(float* __restrict__ out) {
    int t = blockIdx.x, tid = threadIdx.x, lane = tid & 31;
    __shared__ float sinv;
    if (tid < 32) {
        float s = 0.f;
        for (int b = lane; b < LBLK; b += 32) s += g_lpart[b * 64 + t];
        s = warp_sum(s);
        if (!lane) sinv = 1.f / s;
    }
    __syncthreads();
    float inv = sinv;
    float4* row = (float4*)(out + (size_t)t * Vi);
    for (int i = tid; i < Vi / 4; i += 256) {
        float4 v = row[i];
        v.x *= inv; v.y *= inv; v.z *= inv; v.w *= inv;
        row[i] = v;
    }
}

// ---------------- launch ----------------
extern "C" void kernel_launch(void* const* d_in, const int* in_sizes, int n_in,
                              void* d_out, int out_size) {
    const float* hq  = (const float*)d_in[0];
    const float* hp  = (const float*)d_in[1];
    const float* ans = (const float*)d_in[2];
    const float* vv  = (const float*)d_in[3];
    const float* wd  = (const float*)d_in[4];
    const float* bd  = (const float*)d_in[5];
    const float* wa  = (const float*)d_in[6];
    const float* ua  = (const float*)d_in[7];
    const float* wr  = (const float*)d_in[8];
    const float* ur  = (const float*)d_in[9];
    const float* vr  = (const float*)d_in[10];
    const float* wo  = (const float*)d_in[11];
    const float* wih = (const float*)d_in[12];
    const float* whh = (const float*)d_in[13];
    const float* bih = (const float*)d_in[14];
    const float* bhh = (const float*)d_in[15];
    float* out = (float*)d_out;

    float *p_pre_gi, *p_pre_r;
    __half2 *p_whh, *p_wih2, *p_wa, *p_ur, *p_vr, *p_wo;
    cudaGetSymbolAddress((void**)&p_pre_gi, g_pre_gi);
    cudaGetSymbolAddress((void**)&p_pre_r,  g_pre_r);
    cudaGetSymbolAddress((void**)&p_whh,  g_whh_h);
    cudaGetSymbolAddress((void**)&p_wih2, g_wih2_h);
    cudaGetSymbolAddress((void**)&p_wa,   g_wa_h);
    cudaGetSymbolAddress((void**)&p_ur,   g_ur_h);
    cudaGetSymbolAddress((void**)&p_vr,   g_vr_h);
    cudaGetSymbolAddress((void**)&p_wo,   g_wo_h);

    // fused prologue: pre-GEMMs + pooled-h partials + all weight conversions
    k_prep<<<PREPB, 256>>>(wih, bih, wr, ans, hq, hp,
                           whh, wa, ur, vr, wo,
                           p_pre_gi, p_pre_r,
                           p_whh, p_wih2, p_wa, p_ur, p_vr, p_wo);
    k_hreduce<<<4, 256>>>();
    k_uah_d0<<<256, 256>>>(ua, hq, hp, wd, bd);

    // fused sequential decode (byte-balanced roles)
    k_decode<<<NBLK, NTHR>>>(vv, bhh);

    // output
    k_logits<<<LBLK, 256>>>(out);
    k_scale<<<Li, 256>>>(out);
}

// round 17
// speedup vs baseline: 1.2604x; 1.2604x over previous
#include <cuda_runtime.h>
#include <cuda_fp16.h>
#include <math.h>

// Dimensions
#define D2i 1024   // 2H
#define D4i 2048   // 4H
#define G3i 6144   // 3*D4
#define Hi  512
#define Vi  32000
#define Mi  32
#define Ni  4096
#define Li  64

#define NBLK 148      // one block per SM — use the whole chip
#define NTHR 1024
#define LBLK 500      // logits blocks (Vi/64)

// ---------------- device scratch ----------------
__device__ float  g_hpart[128][D2i];
__device__ float  g_h[D2i];
__device__ float  g_uah[D2i];
__device__ float  g_hbuf[2][D4i];
__device__ float2 g_srow[D2i];
__device__ float  g_pre_gi[Li][G3i];
__device__ float  g_pre_r[Li][D2i];
__device__ float  g_R[Li][Hi];
__device__ float  g_lpart[LBLK * Li];
__device__ unsigned int g_bar_count = 0;
__device__ volatile unsigned int g_bar_gen = 0;

// fp16 weights, contiguous rows, gate/pair-interleaved ROW ORDER:
__device__ __half g_whh_h [G3i * D4i];   // dst row 3k+g = whh row (g*2048+k)
__device__ __half g_wih2_h[G3i * D2i];   // dst row 3k+g = wih row (g*2048+k), cols D2..D4
__device__ __half g_wa_h  [D2i * D2i];
__device__ __half g_ur_h  [D2i * D2i];   // dst row 2i+s = ur row (s*512+i)
__device__ __half g_vr_h  [D2i * D4i];   // dst row 2i+s = vr row (s*512+i)
__device__ __half g_wo_h  [Vi * Hi];     // plain row-major half copy of w_o

__device__ __forceinline__ float warp_sum(float v) {
#pragma unroll
    for (int o = 16; o; o >>= 1) v += __shfl_xor_sync(0xffffffffu, v, o);
    return v;
}

// atomic grid barrier: one arrival atomic + one polled line, nanosleep backoff
__device__ __forceinline__ void grid_bar() {
    __threadfence();
    __syncthreads();
    if (threadIdx.x == 0) {
        unsigned int gen = g_bar_gen;
        if (atomicAdd(&g_bar_count, 1u) == NBLK - 1) {
            g_bar_count = 0;
            __threadfence();
            g_bar_gen = gen + 1;
        } else {
            while (g_bar_gen == gen) { __nanosleep(32); }
        }
    }
    __syncthreads();
}

// fp16 dot, HFMA2, per-lane partial (caller warp_sums). Weights via __ldcg.
template<int NM>
__device__ __forceinline__ float dot_hh(const uint4* __restrict__ w,
                                        const uint4* __restrict__ v, int lane) {
    float acc = 0.f;
#pragma unroll
    for (int m = 0; m < NM; m += 2) {
        uint4 u0 = __ldcg(&w[lane + 32 * m]);
        uint4 x0 = v[lane + 32 * m];
        uint4 u1 = __ldcg(&w[lane + 32 * (m + 1)]);
        uint4 x1 = v[lane + 32 * (m + 1)];
        const __half2* a = (const __half2*)&u0;
        const __half2* b = (const __half2*)&x0;
        __half2 s = __hmul2(a[0], b[0]);
        s = __hfma2(a[1], b[1], s);
        s = __hfma2(a[2], b[2], s);
        s = __hfma2(a[3], b[3], s);
        const __half2* c = (const __half2*)&u1;
        const __half2* d = (const __half2*)&x1;
        s = __hfma2(c[0], d[0], s);
        s = __hfma2(c[1], d[1], s);
        s = __hfma2(c[2], d[2], s);
        s = __hfma2(c[3], d[3], s);
        float2 f = __half22float2(s);
        acc += f.x + f.y;
    }
    return acc;
}
// one weight row vs two smem vectors (weights read once), per-lane partial pair
template<int NM>
__device__ __forceinline__ float2 dot_hh2(const uint4* __restrict__ w,
                                          const uint4* __restrict__ v0,
                                          const uint4* __restrict__ v1, int lane) {
    float a0 = 0.f, a1 = 0.f;
#pragma unroll
    for (int m = 0; m < NM; m += 2) {
        uint4 u0 = __ldcg(&w[lane + 32 * m]);
        uint4 u1 = __ldcg(&w[lane + 32 * (m + 1)]);
        uint4 p0 = v0[lane + 32 * m], p1 = v0[lane + 32 * (m + 1)];
        uint4 q0 = v1[lane + 32 * m], q1 = v1[lane + 32 * (m + 1)];
        const __half2* a = (const __half2*)&u0;
        const __half2* c = (const __half2*)&u1;
        {
            const __half2* b0 = (const __half2*)&p0;
            const __half2* b1 = (const __half2*)&p1;
            __half2 s = __hmul2(a[0], b0[0]);
            s = __hfma2(a[1], b0[1], s);
            s = __hfma2(a[2], b0[2], s);
            s = __hfma2(a[3], b0[3], s);
            s = __hfma2(c[0], b1[0], s);
            s = __hfma2(c[1], b1[1], s);
            s = __hfma2(c[2], b1[2], s);
            s = __hfma2(c[3], b1[3], s);
            float2 f = __half22float2(s);
            a0 += f.x + f.y;
        }
        {
            const __half2* b0 = (const __half2*)&q0;
            const __half2* b1 = (const __half2*)&q1;
            __half2 s = __hmul2(a[0], b0[0]);
            s = __hfma2(a[1], b0[1], s);
            s = __hfma2(a[2], b0[2], s);
            s = __hfma2(a[3], b0[3], s);
            s = __hfma2(c[0], b1[0], s);
            s = __hfma2(c[1], b1[1], s);
            s = __hfma2(c[2], b1[2], s);
            s = __hfma2(c[3], b1[3], s);
            float2 f = __half22float2(s);
            a1 += f.x + f.y;
        }
    }
    return make_float2(a0, a1);
}

// ---------------- conversion helper (row-reordered, contiguous elements) ----------------
__device__ __forceinline__ void cvt_seg(const float* __restrict__ src, __half2* __restrict__ dst,
                                        int rows, int w2shift, int srcLd, int srcOff,
                                        int nG, int G, int gtid, int gstride) {
    int total = rows << w2shift;
    int mask = (1 << w2shift) - 1;
    for (int idx = gtid; idx < total; idx += gstride) {
        int r = idx >> w2shift, e2 = idx & mask;
        int sr = (r % nG) * G + r / nG;
        float2 f = *(const float2*)(src + (size_t)sr * srcLd + srcOff + 2 * e2);
        dst[idx] = __floats2half2_rn(f.x, f.y);
    }
}

// ---------------- fused prologue: pre-GEMMs [0,448) + hpart [448,576) + cvt [576,1168) ----
#define PREPB 1168
#define CVT0  576
__global__ void k_prep(const float* __restrict__ wih, const float* __restrict__ bih,
                       const float* __restrict__ wr,  const float* __restrict__ ans,
                       const float* __restrict__ hq,  const float* __restrict__ hp,
                       const float* __restrict__ whh, const float* __restrict__ wa,
                       const float* __restrict__ ur,  const float* __restrict__ vr,
                       const float* __restrict__ wo,
                       float* __restrict__ pg, float* __restrict__ pr,
                       __half2* p_whh, __half2* p_wih2, __half2* p_wa,
                       __half2* p_ur, __half2* p_vr, __half2* p_wo) {
    __shared__ float As[16][65];
    __shared__ __align__(16) float BsT[64][68];
    int blk = blockIdx.x;
    int tid = threadIdx.x;

    if (blk < 448) {
        // ---- pre-GEMMs (16-row tiles) ----
        const float* A; const float* bias; float* C;
        int lda, crows, k0;
        if (blk < 384) { A = wih; lda = D4i; bias = bih; C = pg; crows = G3i; k0 = blk * 16; }
        else           { A = wr;  lda = D2i; bias = 0;   C = pr; crows = D2i; k0 = (blk - 384) * 16; }
        int tx = tid & 15, ty = tid >> 4;
        float acc[4] = {0.f, 0.f, 0.f, 0.f};
        for (int ch = 0; ch < D2i; ch += 64) {
            for (int i = tid; i < 16 * 64; i += 256) {
                int r = i >> 6, c = i & 63;
                As[r][c] = A[(size_t)(k0 + r) * lda + ch + c];
            }
            for (int i = tid; i < 64 * 64; i += 256) {
                int t = i >> 6, c = i & 63;
                BsT[c][t] = ans[(size_t)t * D2i + ch + c];
            }
            __syncthreads();
#pragma unroll 16
            for (int p = 0; p < 64; p++) {
                float4 bv = *(const float4*)&BsT[p][tx * 4];
                float a = As[ty][p];
                acc[0] += a * bv.x; acc[1] += a * bv.y; acc[2] += a * bv.z; acc[3] += a * bv.w;
            }
            __syncthreads();
        }
        int k = k0 + ty;
        float bb = bias ? bias[k] : 0.f;
#pragma unroll
        for (int j = 0; j < 4; j++)
            C[(size_t)(tx * 4 + j) * crows + k] = acc[j] + bb;
    } else if (blk < CVT0) {
        // ---- pooled-h partials ----
        int b = blk - 448;
        float acc[4] = {0.f, 0.f, 0.f, 0.f};
        for (int r = 0; r < 32; r++) {
            const float* row = hp + (size_t)(b * 32 + r) * D2i;
#pragma unroll
            for (int c = 0; c < 4; c++) acc[c] += row[tid + 256 * c];
        }
        if (b == 0) {
            for (int r = 0; r < Mi; r++) {
                const float* row = hq + (size_t)r * D2i;
#pragma unroll
                for (int c = 0; c < 4; c++) acc[c] += row[tid + 256 * c];
            }
        }
#pragma unroll
        for (int c = 0; c < 4; c++) g_hpart[b][tid + 256 * c] = acc[c];
    } else {
        // ---- weight conversions (grid-strided over the cvt section) ----
        int gtid = (blk - CVT0) * 256 + tid;
        int gstride = (PREPB - CVT0) * 256;
        cvt_seg(whh, p_whh,  G3i, 10, D4i, 0,    3, D4i, gtid, gstride);
        cvt_seg(wih, p_wih2, G3i,  9, D4i, D2i,  3, D4i, gtid, gstride);
        cvt_seg(wa,  p_wa,   D2i,  9, D2i, 0,    1, D2i, gtid, gstride);
        cvt_seg(ur,  p_ur,   D2i,  9, D2i, 0,    2, Hi,  gtid, gstride);
        cvt_seg(vr,  p_vr,   D2i, 10, D4i, 0,    2, Hi,  gtid, gstride);
        cvt_seg(wo,  p_wo,   Vi,   8, Hi,  0,    1, Vi,  gtid, gstride);
    }
}

__global__ void k_hreduce() {
    int j = blockIdx.x * 256 + threadIdx.x;
    float s = 0.f;
    for (int b = 0; b < 128; b++) s += g_hpart[b][j];
    g_h[j] = s;
}

// ---------------- uah + d0 (fp32) ----------------
__device__ __forceinline__ float dot4f(float4 a, float4 b) {
    return a.x * b.x + a.y * b.y + a.z * b.z + a.w * b.w;
}
__global__ void k_uah_d0(const float* __restrict__ ua,
                         const float* __restrict__ hq, const float* __restrict__ hp,
                         const float* __restrict__ wd, const float* __restrict__ bd) {
    int lane = threadIdx.x & 31;
    if (blockIdx.x < 128) {
        int k = blockIdx.x * 8 + (threadIdx.x >> 5);
        const float4* row = (const float4*)(ua + (size_t)k * D2i);
        const float4* h4  = (const float4*)g_h;
        float acc = 0.f;
#pragma unroll
        for (int m = 0; m < 8; m++) acc += dot4f(row[lane + 32 * m], h4[lane + 32 * m]);
        acc = warp_sum(acc);
        if (!lane) g_uah[k] = acc;
    } else {
        int k = (blockIdx.x - 128) * 8 + (threadIdx.x >> 5);
        const float4* row = (const float4*)(wd + (size_t)k * D2i);
        const float4* q4 = (const float4*)hq;
        const float4* p4 = (const float4*)hp;
        float a0 = 0.f, a1 = 0.f;
#pragma unroll
        for (int m = 0; m < 8; m++) {
            float4 w = row[lane + 32 * m];
            a0 += dot4f(w, q4[lane + 32 * m]);
            a1 += dot4f(w, p4[lane + 32 * m]);
        }
        a0 = warp_sum(a0); a1 = warp_sum(a1);
        if (!lane) {
            float b = bd[k];
            g_hbuf[0][k]       = tanhf(a0 + b);
            g_hbuf[0][D2i + k] = tanhf(a1 + b);
        }
    }
}

// ---------------- persistent decode (round-15 structure, NBLK=148) ----------------
// tau = wid*NBLK + blockIdx (0..4735; roles for tau<3584, rest barrier-only):
//   GRU  (tau<2048,k=tau): whh 3 rows @ d + wih2 3 rows @ (d0,d1); post: combine+cell
//   ATTN (2048..3071):     wa row @ (d0,d1) -> score
//   R    (3072..3583,i):   finish R[t-1] + new ur@(d0,d1); post: fold A0/A1
__global__ void __launch_bounds__(NTHR, 1) k_decode(
    const float* __restrict__ vv, const float* __restrict__ bhh)
{
    __shared__ __align__(16) __half sdh[D4i];
    __shared__ float sred0[32], sred1[32];

    int tid = threadIdx.x, lane = tid & 31, wid = tid >> 5;
    int tau = wid * NBLK + blockIdx.x;

    float hr = 0.f, hz = 0.f, hn = 0.f;
    float2 gr2 = make_float2(0.f, 0.f), gz2 = gr2, gn2 = gr2;
    float puLo = 0.f, puHi = 0.f;

    for (int t = 0; t < Li; t++) {
        int p = t & 1, q = p ^ 1;
        for (int j = tid; j < D4i; j += NTHR)
            sdh[j] = __float2half(__ldcg(&g_hbuf[p][j]));
        __syncthreads();
        const uint4* vd  = (const uint4*)sdh;
        const uint4* vd0 = vd;
        const uint4* vd1 = (const uint4*)(sdh + D2i);

        if (tau < 2048) {
            const uint4* wh = (const uint4*)(g_whh_h + (size_t)tau * 3 * D4i);
            hr = dot_hh<8>(wh,                 vd, lane);
            hz = dot_hh<8>(wh + (D4i >> 3),    vd, lane);
            hn = dot_hh<8>(wh + (D4i >> 2),    vd, lane);
            const uint4* pw = (const uint4*)(g_wih2_h + (size_t)tau * 3 * D2i);
            gr2 = dot_hh2<4>(pw,                vd0, vd1, lane);
            gz2 = dot_hh2<4>(pw + (D2i >> 3),   vd0, vd1, lane);
            gn2 = dot_hh2<4>(pw + (D2i >> 2),   vd0, vd1, lane);
        } else if (tau < 3072) {
            int k = tau - 2048;
            const uint4* w = (const uint4*)(g_wa_h + (size_t)k * D2i);
            float2 s = dot_hh2<4>(w, vd0, vd1, lane);
            s.x = warp_sum(s.x); s.y = warp_sum(s.y);
            if (!lane) {
                float vk = vv[k], uh = g_uah[k];
                float2 o;
                o.x = vk * tanhf(s.x + uh);
                o.y = vk * tanhf(s.y + uh);
                __stcg(&g_srow[k], o);
            }
        } else if (tau < 3584) {
            int i = tau - 3072;
            if (t > 0) {
                const uint4* vp = (const uint4*)(g_vr_h + (size_t)i * 2 * D4i);
                float lo = warp_sum(puLo + dot_hh<8>(vp,              vd, lane));
                float hi = warp_sum(puHi + dot_hh<8>(vp + (D4i >> 3), vd, lane));
                if (!lane) {
                    int r = t - 1;
                    g_R[r][i] = fmaxf(g_pre_r[r][i] + lo, g_pre_r[r][i + Hi] + hi);
                }
            }
            const uint4* up = (const uint4*)(g_ur_h + (size_t)i * 2 * D2i);
            float2 uLo = dot_hh2<4>(up,              vd0, vd1, lane);
            float2 uHi = dot_hh2<4>(up + (D2i >> 3), vd0, vd1, lane);
            puLo = uLo.x; puHi = uHi.x;
            gr2.x = uLo.y; gr2.y = uHi.y;   // scratch for R warps
        }
        grid_bar();

        // redundant deterministic score reduce
        float2 sv = __ldcg(&g_srow[tid]);          // NTHR == D2i
        float v0 = warp_sum(sv.x);
        float v1 = warp_sum(sv.y);
        if (!lane) { sred0[wid] = v0; sred1[wid] = v1; }
        __syncthreads();
        float s0 = 0.f, s1 = 0.f;
#pragma unroll
        for (int i2 = 0; i2 < 32; i2++) { s0 += sred0[i2]; s1 += sred1[i2]; }
        float mx = fmaxf(s0, s1);
        float e0 = expf(s0 - mx), e1 = expf(s1 - mx);
        float inv = 1.f / (e0 + e1);
        float A0 = e0 * inv, A1 = e1 * inv;

        if (tau < 2048) {
            int k = tau;
            float Sr  = warp_sum(A0 * gr2.x + A1 * gr2.y + hr);
            float Sz  = warp_sum(A0 * gz2.x + A1 * gz2.y + hz);
            float Sgn = warp_sum(A0 * gn2.x + A1 * gn2.y);
            float Shn = warp_sum(hn);
            if (!lane) {
                float ir = g_pre_gi[t][k]           + Sr + bhh[k];
                float iz = g_pre_gi[t][k + D4i]     + Sz + bhh[k + D4i];
                float R = 1.f / (1.f + expf(-ir));
                float Z = 1.f / (1.f + expf(-iz));
                float Nn = tanhf(g_pre_gi[t][k + 2 * D4i] + Sgn + R * (Shn + bhh[k + 2 * D4i]));
                float dk = __ldcg(&g_hbuf[p][k]);
                __stcg(&g_hbuf[q][k], (1.f - Z) * Nn + Z * dk);
            }
        } else if (tau >= 3072 && tau < 3584) {
            puLo = A0 * puLo + A1 * gr2.x;
            puHi = A0 * puHi + A1 * gr2.y;
        }
        grid_bar();
    }

    // tail: R[63] with carried partials and h_64 (g_hbuf[0])
    for (int j = tid; j < D4i; j += NTHR)
        sdh[j] = __float2half(__ldcg(&g_hbuf[0][j]));
    __syncthreads();
    if (tau >= 3072 && tau < 3584) {
        int i = tau - 3072;
        const uint4* vd = (const uint4*)sdh;
        const uint4* vp = (const uint4*)(g_vr_h + (size_t)i * 2 * D4i);
        float lo = warp_sum(puLo + dot_hh<8>(vp,              vd, lane));
        float hi = warp_sum(puHi + dot_hh<8>(vp + (D4i >> 3), vd, lane));
        if (!lane)
            g_R[Li - 1][i] = fmaxf(g_pre_r[Li - 1][i] + lo, g_pre_r[Li - 1][i + Hi] + hi);
    }
}

// ---------------- logits GEMM: fp16 weights, HFMA2, exp epilogue + partial sums ----------
__global__ void k_logits(float* __restrict__ out) {
    __shared__ __align__(16) __half2 As[64][33];    // k rows x 32 half2 (+pad)
    __shared__ __align__(16) __half2 BsT[32][68];   // p x t (68 half2 = 17 uint4)
    __shared__ float ps[64][17];
    const __half2* wo2 = (const __half2*)g_wo_h;
    const float* Rm = (const float*)g_R;
    int k0 = blockIdx.x * 64;
    int tid = threadIdx.x;
    int tx = tid & 15, ty = tid >> 4;
    float accf[4][4];
#pragma unroll
    for (int i = 0; i < 4; i++)
#pragma unroll
        for (int j = 0; j < 4; j++) accf[i][j] = 0.f;

    const __half2 hz2 = __float2half2_rn(0.f);
    for (int chunk = 0; chunk < 8; chunk++) {       // 8 x 64 ch = 512
        for (int i = tid; i < 64 * 32; i += 256) {
            int r = i >> 5, c = i & 31;
            As[r][c] = wo2[(size_t)(k0 + r) * (Hi / 2) + chunk * 32 + c];
        }
        for (int i = tid; i < 64 * 32; i += 256) {
            int t = i >> 5, c = i & 31;
            float2 f = *(const float2*)(Rm + (size_t)t * Hi + chunk * 64 + 2 * c);
            BsT[c][t] = __floats2half2_rn(f.x, f.y);
        }
        __syncthreads();
        __half2 acch[4][4];
#pragma unroll
        for (int i = 0; i < 4; i++)
#pragma unroll
            for (int j = 0; j < 4; j++) acch[i][j] = hz2;
#pragma unroll
        for (int p = 0; p < 32; p++) {
            uint4 bvu = *(const uint4*)&BsT[p][tx * 4];
            const __half2* bv = (const __half2*)&bvu;
            __half2 av0 = As[ty * 4 + 0][p];
            __half2 av1 = As[ty * 4 + 1][p];
            __half2 av2 = As[ty * 4 + 2][p];
            __half2 av3 = As[ty * 4 + 3][p];
#pragma unroll
            for (int j = 0; j < 4; j++) {
                acch[0][j] = __hfma2(av0, bv[j], acch[0][j]);
                acch[1][j] = __hfma2(av1, bv[j], acch[1][j]);
                acch[2][j] = __hfma2(av2, bv[j], acch[2][j]);
                acch[3][j] = __hfma2(av3, bv[j], acch[3][j]);
            }
            if ((p & 7) == 7) {
#pragma unroll
                for (int i = 0; i < 4; i++)
#pragma unroll
                    for (int j = 0; j < 4; j++) {
                        float2 f = __half22float2(acch[i][j]);
                        accf[i][j] += f.x + f.y;
                        acch[i][j] = hz2;
                    }
            }
        }
        __syncthreads();
    }
    float colsum[4] = {0.f, 0.f, 0.f, 0.f};
#pragma unroll
    for (int i = 0; i < 4; i++) {
        int k = k0 + ty * 4 + i;
#pragma unroll
        for (int j = 0; j < 4; j++) {
            float e = expf(accf[i][j]);
            out[(size_t)(tx * 4 + j) * Vi + k] = e;
            colsum[j] += e;
        }
    }
#pragma unroll
    for (int j = 0; j < 4; j++) ps[tx * 4 + j][ty] = colsum[j];
    __syncthreads();
    if (tid < 64) {
        float s = 0.f;
#pragma unroll
        for (int y = 0; y < 16; y++) s += ps[tid][y];
        g_lpart[blockIdx.x * 64 + tid] = s;
    }
}

__global__ void k_scale(float* __restrict__ out) {
    int t = blockIdx.x, tid = threadIdx.x, lane = tid & 31;
    __shared__ float sinv;
    if (tid < 32) {
        float s = 0.f;
        for (int b = lane; b < LBLK; b += 32) s += g_lpart[b * 64 + t];
        s = warp_sum(s);
        if (!lane) sinv = 1.f / s;
    }
    __syncthreads();
    float inv = sinv;
    float4* row = (float4*)(out + (size_t)t * Vi);
    for (int i = tid; i < Vi / 4; i += 256) {
        float4 v = row[i];
        v.x *= inv; v.y *= inv; v.z *= inv; v.w *= inv;
        row[i] = v;
    }
}

// ---------------- launch ----------------
extern "C" void kernel_launch(void* const* d_in, const int* in_sizes, int n_in,
                              void* d_out, int out_size) {
    const float* hq  = (const float*)d_in[0];
    const float* hp  = (const float*)d_in[1];
    const float* ans = (const float*)d_in[2];
    const float* vv  = (const float*)d_in[3];
    const float* wd  = (const float*)d_in[4];
    const float* bd  = (const float*)d_in[5];
    const float* wa  = (const float*)d_in[6];
    const float* ua  = (const float*)d_in[7];
    const float* wr  = (const float*)d_in[8];
    const float* ur  = (const float*)d_in[9];
    const float* vr  = (const float*)d_in[10];
    const float* wo  = (const float*)d_in[11];
    const float* wih = (const float*)d_in[12];
    const float* whh = (const float*)d_in[13];
    const float* bih = (const float*)d_in[14];
    const float* bhh = (const float*)d_in[15];
    float* out = (float*)d_out;

    float *p_pre_gi, *p_pre_r;
    __half2 *p_whh, *p_wih2, *p_wa, *p_ur, *p_vr, *p_wo;
    cudaGetSymbolAddress((void**)&p_pre_gi, g_pre_gi);
    cudaGetSymbolAddress((void**)&p_pre_r,  g_pre_r);
    cudaGetSymbolAddress((void**)&p_whh,  g_whh_h);
    cudaGetSymbolAddress((void**)&p_wih2, g_wih2_h);
    cudaGetSymbolAddress((void**)&p_wa,   g_wa_h);
    cudaGetSymbolAddress((void**)&p_ur,   g_ur_h);
    cudaGetSymbolAddress((void**)&p_vr,   g_vr_h);
    cudaGetSymbolAddress((void**)&p_wo,   g_wo_h);

    // fused prologue: pre-GEMMs + pooled-h partials + all weight conversions
    k_prep<<<PREPB, 256>>>(wih, bih, wr, ans, hq, hp,
                           whh, wa, ur, vr, wo,
                           p_pre_gi, p_pre_r,
                           p_whh, p_wih2, p_wa, p_ur, p_vr, p_wo);
    k_hreduce<<<4, 256>>>();
    k_uah_d0<<<256, 256>>>(ua, hq, hp, wd, bd);

    // fused sequential decode (round-15 roles, full-chip grid)
    k_decode<<<NBLK, NTHR>>>(vv, bhh);

    // output
    k_logits<<<LBLK, 256>>>(out);
    k_scale<<<Li, 256>>>(out);
}